// round 1
// baseline (speedup 1.0000x reference)
#include <cuda_runtime.h>
#include <math.h>

#define BATCH 8
#define CCH 512
#define SS 1024
#define HWD 32
#define NHD 8
#define HDD 64
#define NGR 32
#define CG 16
#define C8 64
#define C2 256
#define GEPS 1e-6f

// ---------------- static scratch (no allocations allowed) ----------------
__device__ float d_hs   [BATCH*CCH*SS];
__device__ float d_shn  [BATCH*CCH*SS];
__device__ float d_senh [BATCH*CCH*SS];
__device__ float d_a1   [BATCH*C8*SS];
__device__ float d_a2   [BATCH*C8*SS];
__device__ float d_swt  [BATCH*SS];
__device__ float d_q    [BATCH*SS*CCH];
__device__ float d_k    [BATCH*SS*CCH];
__device__ float d_v    [BATCH*SS*CCH];
__device__ float d_qm   [2*BATCH*SS*C2];
__device__ float d_km   [2*BATCH*SS*C2];
__device__ float d_vm   [2*BATCH*SS*C2];
__device__ float d_comb [BATCH*SS*2*CCH];
__device__ float d_f1   [BATCH*SS*CCH];
__device__ float d_fus  [BATCH*SS*CCH];
__device__ float d_fin  [BATCH*SS*CCH];
__device__ float d_sc   [67108864];   // B*NH*S*S = 64M floats
__device__ float d_scm  [16777216];   // 2*B*S*S  = 16M floats

// ---------------- helpers ----------------
__device__ __forceinline__ float blk_sum(float v, float* sb, int tid) {
    sb[tid] = v; __syncthreads();
    for (int o = 128; o > 0; o >>= 1) { if (tid < o) sb[tid] += sb[tid + o]; __syncthreads(); }
    float r = sb[0]; __syncthreads(); return r;
}
__device__ __forceinline__ float blk_max(float v, float* sb, int tid) {
    sb[tid] = v; __syncthreads();
    for (int o = 128; o > 0; o >>= 1) { if (tid < o) sb[tid] = fmaxf(sb[tid], sb[tid + o]); __syncthreads(); }
    float r = sb[0]; __syncthreads(); return r;
}
__device__ __forceinline__ float silu_f(float x) { return x / (1.0f + expf(-x)); }

// ---------------- group norm, channel-major input (B,C,S), optional pos add ----------------
__global__ void gn_cmajor(const float* __restrict__ x, const float* __restrict__ g,
                          const float* __restrict__ be, const float* __restrict__ pos,
                          float* __restrict__ y) {
    __shared__ float sb[256];
    int tid = threadIdx.x;
    int b = blockIdx.x / NGR, gi = blockIdx.x % NGR;
    long base = (long)b * CCH * SS + (long)gi * CG * SS;
    float s1 = 0.f, s2 = 0.f;
    for (int i = tid; i < CG * SS; i += 256) { float v = x[base + i]; s1 += v; s2 += v * v; }
    s1 = blk_sum(s1, sb, tid);
    s2 = blk_sum(s2, sb, tid);
    float mu = s1 / (float)(CG * SS);
    float var = s2 / (float)(CG * SS) - mu * mu;
    float inv = rsqrtf(var + GEPS);
    for (int i = tid; i < CG * SS; i += 256) {
        int cl = i >> 10, s = i & 1023;
        int c = gi * CG + cl;
        float v = (x[base + i] - mu) * inv * g[c] + be[c];
        if (pos) v += pos[(long)c * SS + s];
        y[base + i] = v;
    }
}

// ---------------- group norm, token-major input (B,S,C), + residual, out (B,C,S) ----------------
__global__ void gn_post_k(const float* __restrict__ xt, const float* __restrict__ g,
                          const float* __restrict__ be, const float* __restrict__ resid,
                          float* __restrict__ y) {
    __shared__ float sb[256];
    int tid = threadIdx.x;
    int b = blockIdx.x / NGR, gi = blockIdx.x % NGR;
    long tbase = (long)b * SS * CCH + gi * CG;
    float s1 = 0.f, s2 = 0.f;
    for (int i = tid; i < CG * SS; i += 256) {
        int s = i >> 4, cl = i & 15;
        float v = xt[tbase + (long)s * CCH + cl]; s1 += v; s2 += v * v;
    }
    s1 = blk_sum(s1, sb, tid);
    s2 = blk_sum(s2, sb, tid);
    float mu = s1 / (float)(CG * SS);
    float var = s2 / (float)(CG * SS) - mu * mu;
    float inv = rsqrtf(var + GEPS);
    for (int i = tid; i < CG * SS; i += 256) {
        int s = i >> 4, cl = i & 15;
        int c = gi * CG + cl;
        float v = (xt[tbase + (long)s * CCH + cl] - mu) * inv * g[c] + be[c];
        long oidx = (long)b * CCH * SS + (long)c * SS + s;
        y[oidx] = v + resid[oidx];
    }
}

// ---------------- generic batched GEMM: 64x64 tile, Kt=16, 256 thr, 4x4/thr ----------------
// MODE 0 (NT): A[m*lda+k],  B[n*ldb+k]
// MODE 1 (TN): A[k*lda+m],  B[n*ldb+k]
// MODE 2 (NN): A[m*lda+k],  B[k*ldb+n]
// batch offset: (z/innerCnt)*outer + (z%innerCnt)*inner for A, B, Y
template<int MODE>
__global__ void gemm64(const float* __restrict__ A, long aOuter, long aInner,
                       const float* __restrict__ Bm, long bOuter, long bInner,
                       const float* __restrict__ bias,
                       float* __restrict__ Y, long yOuter, long yInner,
                       int innerCnt, int K, int lda, int ldb, int ldy,
                       float scale, int act) {
    __shared__ float As[16][68];
    __shared__ float Bs[16][68];
    int z = blockIdx.z;
    const float* Ab = A  + (long)(z / innerCnt) * aOuter + (long)(z % innerCnt) * aInner;
    const float* Bb = Bm + (long)(z / innerCnt) * bOuter + (long)(z % innerCnt) * bInner;
    float*       Yb = Y  + (long)(z / innerCnt) * yOuter + (long)(z % innerCnt) * yInner;
    int m0 = blockIdx.x * 64, n0 = blockIdx.y * 64;
    int tid = threadIdx.x, tx = tid & 15, ty = tid >> 4;
    float acc[4][4] = {};

    for (int k0 = 0; k0 < K; k0 += 16) {
        if (MODE == 1) { // A col-major (k,m)
            int mm = tid & 63, kks = tid >> 6;
            #pragma unroll
            for (int kk = kks; kk < 16; kk += 4)
                As[kk][mm] = Ab[(long)(k0 + kk) * lda + m0 + mm];
        } else {         // A row-major (m,k)
            int kk = tid & 15, mm = tid >> 4;
            #pragma unroll
            for (int r = 0; r < 4; r++)
                As[kk][mm + 16 * r] = Ab[(long)(m0 + mm + 16 * r) * lda + k0 + kk];
        }
        if (MODE == 2) { // B row-major (k,n)
            int nn = tid & 63, kks = tid >> 6;
            #pragma unroll
            for (int kk = kks; kk < 16; kk += 4)
                Bs[kk][nn] = Bb[(long)(k0 + kk) * ldb + n0 + nn];
        } else {         // B row-major (n,k)
            int kk = tid & 15, nn = tid >> 4;
            #pragma unroll
            for (int r = 0; r < 4; r++)
                Bs[kk][nn + 16 * r] = Bb[(long)(n0 + nn + 16 * r) * ldb + k0 + kk];
        }
        __syncthreads();
        #pragma unroll
        for (int kk = 0; kk < 16; kk++) {
            float av[4], bv[4];
            *(float4*)av = *(const float4*)(&As[kk][ty * 4]);
            *(float4*)bv = *(const float4*)(&Bs[kk][tx * 4]);
            #pragma unroll
            for (int i = 0; i < 4; i++)
                #pragma unroll
                for (int j = 0; j < 4; j++)
                    acc[i][j] += av[i] * bv[j];
        }
        __syncthreads();
    }
    #pragma unroll
    for (int i = 0; i < 4; i++) {
        int m = m0 + ty * 4 + i;
        float ov[4];
        #pragma unroll
        for (int j = 0; j < 4; j++) {
            float vv = acc[i][j] * scale;
            if (bias) vv += bias[n0 + tx * 4 + j];
            if (act == 1) vv = silu_f(vv);
            ov[j] = vv;
        }
        *(float4*)&Yb[(long)m * ldy + n0 + tx * 4] = *(float4*)ov;
    }
}

// ---------------- softmax over rows of length 1024 ----------------
__global__ void softmax1024(float* __restrict__ p) {
    __shared__ float sb[256];
    long r = blockIdx.x;
    float* row = p + r * 1024;
    int tid = threadIdx.x;
    float4 v = *(float4*)&row[tid * 4];
    float m = fmaxf(fmaxf(v.x, v.y), fmaxf(v.z, v.w));
    m = blk_max(m, sb, tid);
    v.x = __expf(v.x - m); v.y = __expf(v.y - m);
    v.z = __expf(v.z - m); v.w = __expf(v.w - m);
    float s = v.x + v.y + v.z + v.w;
    s = blk_sum(s, sb, tid);
    float inv = 1.0f / s;
    v.x *= inv; v.y *= inv; v.z *= inv; v.w *= inv;
    *(float4*)&row[tid * 4] = v;
}

// ---------------- conv 1x1 (512 -> 64) + SiLU ----------------
__global__ void conv1_silu(const float* __restrict__ x, const float* __restrict__ w,
                           const float* __restrict__ bias, float* __restrict__ y) {
    __shared__ float ws[8 * 512];
    int tid = threadIdx.x;
    int o0 = blockIdx.y * 8, b = blockIdx.z;
    for (int i = tid; i < 8 * 512; i += 256) ws[i] = w[(long)o0 * 512 + i];
    __syncthreads();
    int s = blockIdx.x * 256 + tid;
    float acc[8];
    #pragma unroll
    for (int oo = 0; oo < 8; oo++) acc[oo] = bias[o0 + oo];
    const float* xb = x + (long)b * CCH * SS + s;
    for (int c = 0; c < 512; c++) {
        float xv = xb[(long)c * SS];
        #pragma unroll
        for (int oo = 0; oo < 8; oo++) acc[oo] += xv * ws[oo * 512 + c];
    }
    #pragma unroll
    for (int oo = 0; oo < 8; oo++)
        y[(long)b * C8 * SS + (long)(o0 + oo) * SS + s] = silu_f(acc[oo]);
}

// ---------------- conv 3x3 (64 -> 64, SAME) + SiLU ----------------
__global__ void conv2_silu(const float* __restrict__ x, const float* __restrict__ w,
                           const float* __restrict__ bias, float* __restrict__ y) {
    __shared__ float ws[8 * 576];
    int tid = threadIdx.x;
    int o0 = blockIdx.y * 8, b = blockIdx.z;
    for (int i = tid; i < 8 * 576; i += 256) ws[i] = w[(long)o0 * 576 + i];
    __syncthreads();
    int s = blockIdx.x * 256 + tid;
    int yy = s >> 5, xx = s & 31;
    float acc[8];
    #pragma unroll
    for (int oo = 0; oo < 8; oo++) acc[oo] = bias[o0 + oo];
    const float* xb = x + (long)b * C8 * SS;
    for (int ci = 0; ci < 64; ci++) {
        #pragma unroll
        for (int ky = 0; ky < 3; ky++) {
            int py = yy + ky - 1;
            if (py < 0 || py >= 32) continue;
            #pragma unroll
            for (int kx = 0; kx < 3; kx++) {
                int px = xx + kx - 1;
                if (px < 0 || px >= 32) continue;
                float av = xb[(long)ci * SS + py * 32 + px];
                #pragma unroll
                for (int oo = 0; oo < 8; oo++)
                    acc[oo] += av * ws[oo * 576 + ci * 9 + ky * 3 + kx];
            }
        }
    }
    #pragma unroll
    for (int oo = 0; oo < 8; oo++)
        y[(long)b * C8 * SS + (long)(o0 + oo) * SS + s] = silu_f(acc[oo]);
}

// ---------------- conv 1x1 (64 -> 1) + sigmoid ----------------
__global__ void conv3_sig(const float* __restrict__ x, const float* __restrict__ w,
                          const float* __restrict__ bias, float* __restrict__ y) {
    int idx = blockIdx.x * 256 + threadIdx.x;   // over B*S
    int b = idx >> 10, s = idx & 1023;
    float acc = bias[0];
    const float* xb = x + (long)b * C8 * SS + s;
    #pragma unroll 8
    for (int i = 0; i < 64; i++) acc += xb[(long)i * SS] * w[i];
    y[idx] = 1.0f / (1.0f + expf(-acc));
}

// ---------------- spatial_enhanced = hs * sw (broadcast over channels) ----------------
__global__ void senh_mul(const float* __restrict__ hs, const float* __restrict__ sw,
                         float* __restrict__ y) {
    long idx = (long)blockIdx.x * 256 + threadIdx.x;   // over B*C*S
    int b = (int)(idx >> 19);
    int s = (int)(idx & 1023);
    y[idx] = hs[idx] * sw[b * 1024 + s];
}

// ---------------- launch ----------------
static float* sym(const void* s) { void* p = nullptr; cudaGetSymbolAddress(&p, s); return (float*)p; }

extern "C" void kernel_launch(void* const* d_in, const int* in_sizes, int n_in,
                              void* d_out, int out_size) {
    (void)in_sizes; (void)n_in; (void)out_size;
    const float* x      = (const float*)d_in[0];
    const float* pre_g  = (const float*)d_in[1];
    const float* pre_b  = (const float*)d_in[2];
    const float* norm_g = (const float*)d_in[3];
    const float* norm_b = (const float*)d_in[4];
    const float* post_g = (const float*)d_in[5];
    const float* post_b = (const float*)d_in[6];
    const float* pos    = (const float*)d_in[7];
    const float* sa_w1  = (const float*)d_in[8];
    const float* sa_b1  = (const float*)d_in[9];
    const float* sa_w2  = (const float*)d_in[10];
    const float* sa_b2  = (const float*)d_in[11];
    const float* sa_w3  = (const float*)d_in[12];
    const float* sa_b3  = (const float*)d_in[13];
    const float* wq     = (const float*)d_in[14];
    const float* wk     = (const float*)d_in[15];
    const float* wv     = (const float*)d_in[16];
    const float* wqm[2] = { (const float*)d_in[17], (const float*)d_in[20] };
    const float* wkm[2] = { (const float*)d_in[18], (const float*)d_in[21] };
    const float* wvm[2] = { (const float*)d_in[19], (const float*)d_in[22] };
    const float* ff_w1  = (const float*)d_in[23];
    const float* ff_b1  = (const float*)d_in[24];
    const float* ff_w2  = (const float*)d_in[25];
    const float* ff_b2  = (const float*)d_in[26];
    const float* out_w  = (const float*)d_in[27];
    const float* out_b  = (const float*)d_in[28];
    float* out = (float*)d_out;

    float *hs = sym(d_hs), *shn = sym(d_shn), *senh = sym(d_senh);
    float *a1 = sym(d_a1), *a2 = sym(d_a2), *sw = sym(d_swt);
    float *q = sym(d_q), *k = sym(d_k), *v = sym(d_v);
    float *qm = sym(d_qm), *km = sym(d_km), *vm = sym(d_vm);
    float *comb = sym(d_comb), *f1 = sym(d_f1), *fus = sym(d_fus), *fin = sym(d_fin);
    float *sc = sym(d_sc), *scm = sym(d_scm);

    // 1. pre group norm + pos emb  -> hs (B,C,S)
    gn_cmajor<<<BATCH * NGR, 256>>>(x, pre_g, pre_b, pos, hs);
    // 2-4. spatial gate convs
    conv1_silu<<<dim3(4, 8, BATCH), 256>>>(hs, sa_w1, sa_b1, a1);
    conv2_silu<<<dim3(4, 8, BATCH), 256>>>(a1, sa_w2, sa_b2, a2);
    conv3_sig<<<BATCH * SS / 256, 256>>>(a2, sa_w3, sa_b3, sw);
    // 5. spatial_enhanced (B,C,S)
    senh_mul<<<BATCH * CCH * SS / 256, 256>>>(hs, sw, senh);
    // 6. mid group norm -> shn (B,C,S)
    gn_cmajor<<<BATCH * NGR, 256>>>(hs, norm_g, norm_b, nullptr, shn);

    // 7-9. Q,K,V = shn^T @ W^T   (TN, per-batch)  -> (B,S,512)
    gemm64<1><<<dim3(16, 8, BATCH), 256>>>(shn, (long)CCH * SS, 0, wq, 0, 0, nullptr,
                                           q, (long)SS * CCH, 0, 1, 512, SS, 512, 512, 1.f, 0);
    gemm64<1><<<dim3(16, 8, BATCH), 256>>>(shn, (long)CCH * SS, 0, wk, 0, 0, nullptr,
                                           k, (long)SS * CCH, 0, 1, 512, SS, 512, 512, 1.f, 0);
    gemm64<1><<<dim3(16, 8, BATCH), 256>>>(shn, (long)CCH * SS, 0, wv, 0, 0, nullptr,
                                           v, (long)SS * CCH, 0, 1, 512, SS, 512, 512, 1.f, 0);
    // 10-15. multi-scale projections (q from senh, k/v from shn) -> (branch,B,S,256)
    for (int br = 0; br < 2; br++) {
        long off = (long)br * BATCH * SS * C2;
        gemm64<1><<<dim3(16, 4, BATCH), 256>>>(senh, (long)CCH * SS, 0, wqm[br], 0, 0, nullptr,
                                               qm + off, (long)SS * C2, 0, 1, 512, SS, 512, 256, 1.f, 0);
        gemm64<1><<<dim3(16, 4, BATCH), 256>>>(shn, (long)CCH * SS, 0, wkm[br], 0, 0, nullptr,
                                               km + off, (long)SS * C2, 0, 1, 512, SS, 512, 256, 1.f, 0);
        gemm64<1><<<dim3(16, 4, BATCH), 256>>>(shn, (long)CCH * SS, 0, wvm[br], 0, 0, nullptr,
                                               vm + off, (long)SS * C2, 0, 1, 512, SS, 512, 256, 1.f, 0);
    }

    // 16. std scores (64 batch-heads): Q.Kt / 8
    gemm64<0><<<dim3(16, 16, BATCH * NHD), 256>>>(q, (long)SS * CCH, HDD, k, (long)SS * CCH, HDD, nullptr,
                                                  sc, (long)NHD * SS * SS, (long)SS * SS, NHD,
                                                  HDD, CCH, CCH, SS, 0.125f, 0);
    // 17. softmax
    softmax1024<<<BATCH * NHD * SS, 256>>>(sc);
    // 18. P @ V -> comb[:, :, 0:512]
    gemm64<2><<<dim3(16, 1, BATCH * NHD), 256>>>(sc, (long)NHD * SS * SS, (long)SS * SS,
                                                 v, (long)SS * CCH, HDD, nullptr,
                                                 comb, (long)SS * 2 * CCH, HDD, NHD,
                                                 SS, SS, CCH, 2 * CCH, 1.f, 0);
    // 19. multi scores (16 = 2 branches x 8 batches): Qm.Kmt / 16
    gemm64<0><<<dim3(16, 16, 16), 256>>>(qm, (long)SS * C2, 0, km, (long)SS * C2, 0, nullptr,
                                         scm, (long)SS * SS, 0, 1,
                                         C2, C2, C2, SS, 0.0625f, 0);
    // 20. softmax
    softmax1024<<<16 * SS, 256>>>(scm);
    // 21. Pm @ Vm -> comb[:, :, 512 + branch*256 : ...]
    gemm64<2><<<dim3(16, 4, 16), 256>>>(scm, 8LL * SS * SS, (long)SS * SS,
                                        vm, 8LL * SS * C2, (long)SS * C2, nullptr,
                                        comb + CCH, (long)C2, (long)SS * 2 * CCH, 8,
                                        SS, SS, C2, 2 * CCH, 1.f, 0);
    // 22. ff1: silu(comb @ ff_w1^T + b1)
    gemm64<0><<<dim3(16, 8, BATCH), 256>>>(comb, (long)SS * 2 * CCH, 0, ff_w1, 0, 0, ff_b1,
                                           f1, (long)SS * CCH, 0, 1,
                                           2 * CCH, 2 * CCH, 2 * CCH, CCH, 1.f, 1);
    // 23. ff2
    gemm64<0><<<dim3(16, 8, BATCH), 256>>>(f1, (long)SS * CCH, 0, ff_w2, 0, 0, ff_b2,
                                           fus, (long)SS * CCH, 0, 1,
                                           CCH, CCH, CCH, CCH, 1.f, 0);
    // 24. out proj
    gemm64<0><<<dim3(16, 8, BATCH), 256>>>(fus, (long)SS * CCH, 0, out_w, 0, 0, out_b,
                                           fin, (long)SS * CCH, 0, 1,
                                           CCH, CCH, CCH, CCH, 1.f, 0);
    // 25. post group norm + residual -> out (B,C,H,W)
    gn_post_k<<<BATCH * NGR, 256>>>(fin, post_g, post_b, x, out);
}

// round 2
// speedup vs baseline: 2.0539x; 2.0539x over previous
#include <cuda_runtime.h>
#include <math.h>
#include <stdint.h>

#define BATCH 8
#define CCH 512
#define SS 1024
#define NHD 8
#define HDD 64
#define NGR 32
#define CG 16
#define C8 64
#define C2 256
#define GEPS 1e-6f

// ---------------- static scratch ----------------
__device__ float d_hs   [BATCH*CCH*SS];
__device__ float d_shn  [BATCH*CCH*SS];
__device__ float d_senh [BATCH*CCH*SS];
__device__ float d_a1   [BATCH*C8*SS];
__device__ float d_a2   [BATCH*C8*SS];
__device__ float d_swt  [BATCH*SS];
__device__ float d_q    [BATCH*SS*CCH];
__device__ float d_k    [BATCH*SS*CCH];
__device__ float d_v    [BATCH*SS*CCH];
__device__ float d_qm   [2*BATCH*SS*C2];
__device__ float d_km   [2*BATCH*SS*C2];
__device__ float d_vm   [2*BATCH*SS*C2];
__device__ float d_comb [BATCH*SS*2*CCH];
__device__ float d_f1   [BATCH*SS*CCH];
__device__ float d_fus  [BATCH*SS*CCH];
__device__ float d_fin  [BATCH*SS*CCH];
__device__ float d_sc   [67108864];
__device__ float d_scm  [16777216];

// ---------------- helpers ----------------
__device__ __forceinline__ float blk_sum(float v, float* sb, int tid) {
    sb[tid] = v; __syncthreads();
    for (int o = 128; o > 0; o >>= 1) { if (tid < o) sb[tid] += sb[tid + o]; __syncthreads(); }
    float r = sb[0]; __syncthreads(); return r;
}
__device__ __forceinline__ float blk_max(float v, float* sb, int tid) {
    sb[tid] = v; __syncthreads();
    for (int o = 128; o > 0; o >>= 1) { if (tid < o) sb[tid] = fmaxf(sb[tid], sb[tid + o]); __syncthreads(); }
    float r = sb[0]; __syncthreads(); return r;
}
__device__ __forceinline__ float silu_f(float x) { return x / (1.0f + expf(-x)); }
__device__ __forceinline__ float f2tf(float f) {
    uint32_t u; asm("cvt.rna.tf32.f32 %0, %1;" : "=r"(u) : "f"(f));
    return __uint_as_float(u);
}

// ---------------- group norm, channel-major (B,C,S), optional pos add ----------------
__global__ void gn_cmajor(const float* __restrict__ x, const float* __restrict__ g,
                          const float* __restrict__ be, const float* __restrict__ pos,
                          float* __restrict__ y) {
    __shared__ float sb[256];
    int tid = threadIdx.x;
    int b = blockIdx.x / NGR, gi = blockIdx.x % NGR;
    long base = (long)b * CCH * SS + (long)gi * CG * SS;
    float s1 = 0.f, s2 = 0.f;
    for (int i = tid; i < CG * SS; i += 256) { float v = x[base + i]; s1 += v; s2 += v * v; }
    s1 = blk_sum(s1, sb, tid);
    s2 = blk_sum(s2, sb, tid);
    float mu = s1 / (float)(CG * SS);
    float var = s2 / (float)(CG * SS) - mu * mu;
    float inv = rsqrtf(var + GEPS);
    for (int i = tid; i < CG * SS; i += 256) {
        int cl = i >> 10, s = i & 1023;
        int c = gi * CG + cl;
        float v = (x[base + i] - mu) * inv * g[c] + be[c];
        if (pos) v += pos[(long)c * SS + s];
        y[base + i] = v;
    }
}

// ---------------- group norm token-major + residual, out (B,C,S) ----------------
__global__ void gn_post_k(const float* __restrict__ xt, const float* __restrict__ g,
                          const float* __restrict__ be, const float* __restrict__ resid,
                          float* __restrict__ y) {
    __shared__ float sb[256];
    int tid = threadIdx.x;
    int b = blockIdx.x / NGR, gi = blockIdx.x % NGR;
    long tbase = (long)b * SS * CCH + gi * CG;
    float s1 = 0.f, s2 = 0.f;
    for (int i = tid; i < CG * SS; i += 256) {
        int s = i >> 4, cl = i & 15;
        float v = xt[tbase + (long)s * CCH + cl]; s1 += v; s2 += v * v;
    }
    s1 = blk_sum(s1, sb, tid);
    s2 = blk_sum(s2, sb, tid);
    float mu = s1 / (float)(CG * SS);
    float var = s2 / (float)(CG * SS) - mu * mu;
    float inv = rsqrtf(var + GEPS);
    for (int i = tid; i < CG * SS; i += 256) {
        int s = i >> 4, cl = i & 15;
        int c = gi * CG + cl;
        float v = (xt[tbase + (long)s * CCH + cl] - mu) * inv * g[c] + be[c];
        long oidx = (long)b * CCH * SS + (long)c * SS + s;
        y[oidx] = v + resid[oidx];
    }
}

// =====================================================================
// Tensor-core tf32 GEMM. Block tile 128x64, BK=32, 256 threads (8 warps 4x2),
// warp tile 32x32 (2 m-tiles x 4 n-tiles of m16n8k8).
// MODE 0 (NT): A[m*lda+k],  B[n*ldb+k]
// MODE 1 (TN): A[k*lda+m],  B[n*ldb+k]
// MODE 2 (NN): A[m*lda+k],  B[k*ldb+n]
// batch offset: (z/innerCnt)*outer + (z%innerCnt)*inner
// =====================================================================
template<int MODE>
__global__ __launch_bounds__(256) void gemm_tc(
        const float* __restrict__ A, long aOuter, long aInner,
        const float* __restrict__ Bm, long bOuter, long bInner,
        const float* __restrict__ bias,
        float* __restrict__ Y, long yOuter, long yInner,
        int innerCnt, int K, int lda, int ldb, int ldy,
        float scale, int act) {
    // smem layouts (floats):
    //  A: MODE1 -> k-major [32][136];  MODE0/2 -> m-major [128][36]
    //  B: MODE0/1 -> n-major [64][36]; MODE2   -> k-major [32][68]
    __shared__ float smem[6912];
    float* As = smem;
    float* Bs = smem + (MODE == 1 ? 32 * 136 : 128 * 36);

    int z = blockIdx.z;
    const float* Ab = A  + (long)(z / innerCnt) * aOuter + (long)(z % innerCnt) * aInner;
    const float* Bb = Bm + (long)(z / innerCnt) * bOuter + (long)(z % innerCnt) * bInner;
    float*       Yb = Y  + (long)(z / innerCnt) * yOuter + (long)(z % innerCnt) * yInner;
    int m0 = blockIdx.x * 128, n0 = blockIdx.y * 64;

    int tid = threadIdx.x;
    int w = tid >> 5, lane = tid & 31;
    int wm = w & 3, wn = w >> 2;           // 4 x 2 warp grid
    int g = lane >> 2, tig = lane & 3;
    int rbase = wm * 32, cbase = wn * 32;

    float acc[2][4][4];
    #pragma unroll
    for (int i = 0; i < 2; i++)
        #pragma unroll
        for (int j = 0; j < 4; j++)
            #pragma unroll
            for (int l = 0; l < 4; l++) acc[i][j][l] = 0.f;

    for (int k0 = 0; k0 < K; k0 += 32) {
        // ---- stage A ----
        if (MODE == 1) {
            int mm = (tid & 31) * 4;
            int kb = tid >> 5;
            #pragma unroll
            for (int it = 0; it < 4; it++) {
                int kk = kb + it * 8;
                float4 vv = *(const float4*)&Ab[(long)(k0 + kk) * lda + m0 + mm];
                vv.x = f2tf(vv.x); vv.y = f2tf(vv.y); vv.z = f2tf(vv.z); vv.w = f2tf(vv.w);
                *(float4*)&As[kk * 136 + mm] = vv;
            }
        } else {
            int kk = (tid & 7) * 4;
            int mb = tid >> 3;
            #pragma unroll
            for (int it = 0; it < 4; it++) {
                int mm = mb + it * 32;
                float4 vv = *(const float4*)&Ab[(long)(m0 + mm) * lda + k0 + kk];
                vv.x = f2tf(vv.x); vv.y = f2tf(vv.y); vv.z = f2tf(vv.z); vv.w = f2tf(vv.w);
                *(float4*)&As[mm * 36 + kk] = vv;
            }
        }
        // ---- stage B ----
        if (MODE == 2) {
            int nn = (tid & 15) * 4;
            int kb = tid >> 4;
            #pragma unroll
            for (int it = 0; it < 2; it++) {
                int kk = kb + it * 16;
                float4 vv = *(const float4*)&Bb[(long)(k0 + kk) * ldb + n0 + nn];
                vv.x = f2tf(vv.x); vv.y = f2tf(vv.y); vv.z = f2tf(vv.z); vv.w = f2tf(vv.w);
                *(float4*)&Bs[kk * 68 + nn] = vv;
            }
        } else {
            int kk = (tid & 7) * 4;
            int nb = tid >> 3;
            #pragma unroll
            for (int it = 0; it < 2; it++) {
                int nn = nb + it * 32;
                float4 vv = *(const float4*)&Bb[(long)(n0 + nn) * ldb + k0 + kk];
                vv.x = f2tf(vv.x); vv.y = f2tf(vv.y); vv.z = f2tf(vv.z); vv.w = f2tf(vv.w);
                *(float4*)&Bs[nn * 36 + kk] = vv;
            }
        }
        __syncthreads();

        // ---- compute ----
        #pragma unroll
        for (int ks = 0; ks < 4; ks++) {
            int kk = ks * 8 + tig, kk2 = kk + 4;
            uint32_t af[2][4], bf[4][2];
            #pragma unroll
            for (int mt = 0; mt < 2; mt++) {
                int r = rbase + mt * 16 + g;
                if (MODE == 1) {
                    af[mt][0] = __float_as_uint(As[kk  * 136 + r]);
                    af[mt][1] = __float_as_uint(As[kk  * 136 + r + 8]);
                    af[mt][2] = __float_as_uint(As[kk2 * 136 + r]);
                    af[mt][3] = __float_as_uint(As[kk2 * 136 + r + 8]);
                } else {
                    af[mt][0] = __float_as_uint(As[r       * 36 + kk]);
                    af[mt][1] = __float_as_uint(As[(r + 8) * 36 + kk]);
                    af[mt][2] = __float_as_uint(As[r       * 36 + kk2]);
                    af[mt][3] = __float_as_uint(As[(r + 8) * 36 + kk2]);
                }
            }
            #pragma unroll
            for (int nt = 0; nt < 4; nt++) {
                int cN = cbase + nt * 8 + g;
                if (MODE == 2) {
                    bf[nt][0] = __float_as_uint(Bs[kk  * 68 + cN]);
                    bf[nt][1] = __float_as_uint(Bs[kk2 * 68 + cN]);
                } else {
                    bf[nt][0] = __float_as_uint(Bs[cN * 36 + kk]);
                    bf[nt][1] = __float_as_uint(Bs[cN * 36 + kk2]);
                }
            }
            #pragma unroll
            for (int mt = 0; mt < 2; mt++)
                #pragma unroll
                for (int nt = 0; nt < 4; nt++) {
                    asm volatile(
                        "mma.sync.aligned.m16n8k8.row.col.f32.tf32.tf32.f32 "
                        "{%0,%1,%2,%3},{%4,%5,%6,%7},{%8,%9},{%0,%1,%2,%3};"
                        : "+f"(acc[mt][nt][0]), "+f"(acc[mt][nt][1]),
                          "+f"(acc[mt][nt][2]), "+f"(acc[mt][nt][3])
                        : "r"(af[mt][0]), "r"(af[mt][1]), "r"(af[mt][2]), "r"(af[mt][3]),
                          "r"(bf[nt][0]), "r"(bf[nt][1]));
                }
        }
        __syncthreads();
    }

    // ---- epilogue ----
    #pragma unroll
    for (int mt = 0; mt < 2; mt++) {
        #pragma unroll
        for (int nt = 0; nt < 4; nt++) {
            int r = m0 + rbase + mt * 16 + g;
            int cN = n0 + cbase + nt * 8 + 2 * tig;
            float b0 = bias ? bias[cN] : 0.f;
            float b1 = bias ? bias[cN + 1] : 0.f;
            float v0 = acc[mt][nt][0] * scale + b0;
            float v1 = acc[mt][nt][1] * scale + b1;
            float v2 = acc[mt][nt][2] * scale + b0;
            float v3 = acc[mt][nt][3] * scale + b1;
            if (act == 1) { v0 = silu_f(v0); v1 = silu_f(v1); v2 = silu_f(v2); v3 = silu_f(v3); }
            *(float2*)&Yb[(long)r * ldy + cN]       = make_float2(v0, v1);
            *(float2*)&Yb[(long)(r + 8) * ldy + cN] = make_float2(v2, v3);
        }
    }
}

// ---------------- softmax over rows of length 1024 ----------------
__global__ void softmax1024(float* __restrict__ p) {
    __shared__ float sb[256];
    long r = blockIdx.x;
    float* row = p + r * 1024;
    int tid = threadIdx.x;
    float4 v = *(float4*)&row[tid * 4];
    float m = fmaxf(fmaxf(v.x, v.y), fmaxf(v.z, v.w));
    m = blk_max(m, sb, tid);
    v.x = __expf(v.x - m); v.y = __expf(v.y - m);
    v.z = __expf(v.z - m); v.w = __expf(v.w - m);
    float s = v.x + v.y + v.z + v.w;
    s = blk_sum(s, sb, tid);
    float inv = 1.0f / s;
    v.x *= inv; v.y *= inv; v.z *= inv; v.w *= inv;
    *(float4*)&row[tid * 4] = v;
}

// ---------------- conv 1x1 (512 -> 64) + SiLU ----------------
__global__ void conv1_silu(const float* __restrict__ x, const float* __restrict__ w,
                           const float* __restrict__ bias, float* __restrict__ y) {
    __shared__ float ws[8 * 512];
    int tid = threadIdx.x;
    int o0 = blockIdx.y * 8, b = blockIdx.z;
    for (int i = tid; i < 8 * 512; i += 256) ws[i] = w[(long)o0 * 512 + i];
    __syncthreads();
    int s = blockIdx.x * 256 + tid;
    float acc[8];
    #pragma unroll
    for (int oo = 0; oo < 8; oo++) acc[oo] = bias[o0 + oo];
    const float* xb = x + (long)b * CCH * SS + s;
    for (int c = 0; c < 512; c++) {
        float xv = xb[(long)c * SS];
        #pragma unroll
        for (int oo = 0; oo < 8; oo++) acc[oo] += xv * ws[oo * 512 + c];
    }
    #pragma unroll
    for (int oo = 0; oo < 8; oo++)
        y[(long)b * C8 * SS + (long)(o0 + oo) * SS + s] = silu_f(acc[oo]);
}

// ---------------- conv 3x3 (64 -> 64, SAME) + SiLU ----------------
__global__ void conv2_silu(const float* __restrict__ x, const float* __restrict__ w,
                           const float* __restrict__ bias, float* __restrict__ y) {
    __shared__ float ws[8 * 576];
    int tid = threadIdx.x;
    int o0 = blockIdx.y * 8, b = blockIdx.z;
    for (int i = tid; i < 8 * 576; i += 256) ws[i] = w[(long)o0 * 576 + i];
    __syncthreads();
    int s = blockIdx.x * 256 + tid;
    int yy = s >> 5, xx = s & 31;
    float acc[8];
    #pragma unroll
    for (int oo = 0; oo < 8; oo++) acc[oo] = bias[o0 + oo];
    const float* xb = x + (long)b * C8 * SS;
    for (int ci = 0; ci < 64; ci++) {
        #pragma unroll
        for (int ky = 0; ky < 3; ky++) {
            int py = yy + ky - 1;
            if (py < 0 || py >= 32) continue;
            #pragma unroll
            for (int kx = 0; kx < 3; kx++) {
                int px = xx + kx - 1;
                if (px < 0 || px >= 32) continue;
                float av = xb[(long)ci * SS + py * 32 + px];
                #pragma unroll
                for (int oo = 0; oo < 8; oo++)
                    acc[oo] += av * ws[oo * 576 + ci * 9 + ky * 3 + kx];
            }
        }
    }
    #pragma unroll
    for (int oo = 0; oo < 8; oo++)
        y[(long)b * C8 * SS + (long)(o0 + oo) * SS + s] = silu_f(acc[oo]);
}

// ---------------- conv 1x1 (64 -> 1) + sigmoid ----------------
__global__ void conv3_sig(const float* __restrict__ x, const float* __restrict__ w,
                          const float* __restrict__ bias, float* __restrict__ y) {
    int idx = blockIdx.x * 256 + threadIdx.x;
    int b = idx >> 10, s = idx & 1023;
    float acc = bias[0];
    const float* xb = x + (long)b * C8 * SS + s;
    #pragma unroll 8
    for (int i = 0; i < 64; i++) acc += xb[(long)i * SS] * w[i];
    y[idx] = 1.0f / (1.0f + expf(-acc));
}

// ---------------- spatial_enhanced = hs * sw ----------------
__global__ void senh_mul(const float* __restrict__ hs, const float* __restrict__ sw,
                         float* __restrict__ y) {
    long idx = (long)blockIdx.x * 256 + threadIdx.x;
    int b = (int)(idx >> 19);
    int s = (int)(idx & 1023);
    y[idx] = hs[idx] * sw[b * 1024 + s];
}

// ---------------- launch ----------------
static float* sym(const void* s) { void* p = nullptr; cudaGetSymbolAddress(&p, s); return (float*)p; }

extern "C" void kernel_launch(void* const* d_in, const int* in_sizes, int n_in,
                              void* d_out, int out_size) {
    (void)in_sizes; (void)n_in; (void)out_size;
    const float* x      = (const float*)d_in[0];
    const float* pre_g  = (const float*)d_in[1];
    const float* pre_b  = (const float*)d_in[2];
    const float* norm_g = (const float*)d_in[3];
    const float* norm_b = (const float*)d_in[4];
    const float* post_g = (const float*)d_in[5];
    const float* post_b = (const float*)d_in[6];
    const float* pos    = (const float*)d_in[7];
    const float* sa_w1  = (const float*)d_in[8];
    const float* sa_b1  = (const float*)d_in[9];
    const float* sa_w2  = (const float*)d_in[10];
    const float* sa_b2  = (const float*)d_in[11];
    const float* sa_w3  = (const float*)d_in[12];
    const float* sa_b3  = (const float*)d_in[13];
    const float* wq     = (const float*)d_in[14];
    const float* wk     = (const float*)d_in[15];
    const float* wv     = (const float*)d_in[16];
    const float* wqm[2] = { (const float*)d_in[17], (const float*)d_in[20] };
    const float* wkm[2] = { (const float*)d_in[18], (const float*)d_in[21] };
    const float* wvm[2] = { (const float*)d_in[19], (const float*)d_in[22] };
    const float* ff_w1  = (const float*)d_in[23];
    const float* ff_b1  = (const float*)d_in[24];
    const float* ff_w2  = (const float*)d_in[25];
    const float* ff_b2  = (const float*)d_in[26];
    const float* out_w  = (const float*)d_in[27];
    const float* out_b  = (const float*)d_in[28];
    float* out = (float*)d_out;

    float *hs = sym(d_hs), *shn = sym(d_shn), *senh = sym(d_senh);
    float *a1 = sym(d_a1), *a2 = sym(d_a2), *sw = sym(d_swt);
    float *q = sym(d_q), *k = sym(d_k), *v = sym(d_v);
    float *qm = sym(d_qm), *km = sym(d_km), *vm = sym(d_vm);
    float *comb = sym(d_comb), *f1 = sym(d_f1), *fus = sym(d_fus), *fin = sym(d_fin);
    float *sc = sym(d_sc), *scm = sym(d_scm);

    gn_cmajor<<<BATCH * NGR, 256>>>(x, pre_g, pre_b, pos, hs);
    conv1_silu<<<dim3(4, 8, BATCH), 256>>>(hs, sa_w1, sa_b1, a1);
    conv2_silu<<<dim3(4, 8, BATCH), 256>>>(a1, sa_w2, sa_b2, a2);
    conv3_sig<<<BATCH * SS / 256, 256>>>(a2, sa_w3, sa_b3, sw);
    senh_mul<<<BATCH * CCH * SS / 256, 256>>>(hs, sw, senh);
    gn_cmajor<<<BATCH * NGR, 256>>>(hs, norm_g, norm_b, nullptr, shn);

    // QKV projections (TN)
    gemm_tc<1><<<dim3(8, 8, BATCH), 256>>>(shn, (long)CCH * SS, 0, wq, 0, 0, nullptr,
                                           q, (long)SS * CCH, 0, 1, 512, SS, 512, 512, 1.f, 0);
    gemm_tc<1><<<dim3(8, 8, BATCH), 256>>>(shn, (long)CCH * SS, 0, wk, 0, 0, nullptr,
                                           k, (long)SS * CCH, 0, 1, 512, SS, 512, 512, 1.f, 0);
    gemm_tc<1><<<dim3(8, 8, BATCH), 256>>>(shn, (long)CCH * SS, 0, wv, 0, 0, nullptr,
                                           v, (long)SS * CCH, 0, 1, 512, SS, 512, 512, 1.f, 0);
    // multi-scale projections
    for (int br = 0; br < 2; br++) {
        long off = (long)br * BATCH * SS * C2;
        gemm_tc<1><<<dim3(8, 4, BATCH), 256>>>(senh, (long)CCH * SS, 0, wqm[br], 0, 0, nullptr,
                                               qm + off, (long)SS * C2, 0, 1, 512, SS, 512, 256, 1.f, 0);
        gemm_tc<1><<<dim3(8, 4, BATCH), 256>>>(shn, (long)CCH * SS, 0, wkm[br], 0, 0, nullptr,
                                               km + off, (long)SS * C2, 0, 1, 512, SS, 512, 256, 1.f, 0);
        gemm_tc<1><<<dim3(8, 4, BATCH), 256>>>(shn, (long)CCH * SS, 0, wvm[br], 0, 0, nullptr,
                                               vm + off, (long)SS * C2, 0, 1, 512, SS, 512, 256, 1.f, 0);
    }

    // std scores: Q.Kt / 8  (NT, 64 batch-heads)
    gemm_tc<0><<<dim3(8, 16, BATCH * NHD), 256>>>(q, (long)SS * CCH, HDD, k, (long)SS * CCH, HDD, nullptr,
                                                  sc, (long)NHD * SS * SS, (long)SS * SS, NHD,
                                                  HDD, CCH, CCH, SS, 0.125f, 0);
    softmax1024<<<BATCH * NHD * SS, 256>>>(sc);
    // P @ V (NN)
    gemm_tc<2><<<dim3(8, 1, BATCH * NHD), 256>>>(sc, (long)NHD * SS * SS, (long)SS * SS,
                                                 v, (long)SS * CCH, HDD, nullptr,
                                                 comb, (long)SS * 2 * CCH, HDD, NHD,
                                                 SS, SS, CCH, 2 * CCH, 1.f, 0);
    // multi scores (NT, 16 batch-branches)
    gemm_tc<0><<<dim3(8, 16, 16), 256>>>(qm, (long)SS * C2, 0, km, (long)SS * C2, 0, nullptr,
                                         scm, (long)SS * SS, 0, 1,
                                         C2, C2, C2, SS, 0.0625f, 0);
    softmax1024<<<16 * SS, 256>>>(scm);
    // multi P @ V (NN)
    gemm_tc<2><<<dim3(8, 4, 16), 256>>>(scm, 8LL * SS * SS, (long)SS * SS,
                                        vm, 8LL * SS * C2, (long)SS * C2, nullptr,
                                        comb + CCH, (long)C2, (long)SS * 2 * CCH, 8,
                                        SS, SS, C2, 2 * CCH, 1.f, 0);
    // ff1 (silu)
    gemm_tc<0><<<dim3(8, 8, BATCH), 256>>>(comb, (long)SS * 2 * CCH, 0, ff_w1, 0, 0, ff_b1,
                                           f1, (long)SS * CCH, 0, 1,
                                           2 * CCH, 2 * CCH, 2 * CCH, CCH, 1.f, 1);
    // ff2
    gemm_tc<0><<<dim3(8, 8, BATCH), 256>>>(f1, (long)SS * CCH, 0, ff_w2, 0, 0, ff_b2,
                                           fus, (long)SS * CCH, 0, 1,
                                           CCH, CCH, CCH, CCH, 1.f, 0);
    // out proj
    gemm_tc<0><<<dim3(8, 8, BATCH), 256>>>(fus, (long)SS * CCH, 0, out_w, 0, 0, out_b,
                                           fin, (long)SS * CCH, 0, 1,
                                           CCH, CCH, CCH, CCH, 1.f, 0);
    gn_post_k<<<BATCH * NGR, 256>>>(fin, post_g, post_b, x, out);
}

// round 3
// speedup vs baseline: 2.6048x; 1.2682x over previous
#include <cuda_runtime.h>
#include <math.h>
#include <stdint.h>

#define BATCH 8
#define CCH 512
#define SS 1024
#define NHD 8
#define HDD 64
#define NGR 32
#define CG 16
#define C8 64
#define C2 256
#define GEPS 1e-6f

// ---------------- static scratch ----------------
__device__ float d_hs   [BATCH*CCH*SS];
__device__ float d_shn  [BATCH*CCH*SS];
__device__ float d_senh [BATCH*CCH*SS];
__device__ float d_a1   [BATCH*C8*SS];
__device__ float d_a2   [BATCH*C8*SS];
__device__ float d_swt  [BATCH*SS];
__device__ float d_q    [BATCH*SS*CCH];
__device__ float d_k    [BATCH*SS*CCH];
__device__ float d_v    [BATCH*SS*CCH];
__device__ float d_qm   [2*BATCH*SS*C2];
__device__ float d_km   [2*BATCH*SS*C2];
__device__ float d_vm   [2*BATCH*SS*C2];
__device__ float d_comb [BATCH*SS*2*CCH];
__device__ float d_f1   [BATCH*SS*CCH];
__device__ float d_fus  [BATCH*SS*CCH];
__device__ float d_fin  [BATCH*SS*CCH];
__device__ float d_scm  [16777216];   // 2*B*S*S for multi-scale scores

// ---------------- helpers ----------------
__device__ __forceinline__ float blk_sum(float v, float* sb, int tid) {
    sb[tid] = v; __syncthreads();
    for (int o = 128; o > 0; o >>= 1) { if (tid < o) sb[tid] += sb[tid + o]; __syncthreads(); }
    float r = sb[0]; __syncthreads(); return r;
}
__device__ __forceinline__ float blk_max(float v, float* sb, int tid) {
    sb[tid] = v; __syncthreads();
    for (int o = 128; o > 0; o >>= 1) { if (tid < o) sb[tid] = fmaxf(sb[tid], sb[tid + o]); __syncthreads(); }
    float r = sb[0]; __syncthreads(); return r;
}
__device__ __forceinline__ float silu_f(float x) { return x / (1.0f + expf(-x)); }
__device__ __forceinline__ float f2tf(float f) {
    uint32_t u; asm("cvt.rna.tf32.f32 %0, %1;" : "=r"(u) : "f"(f));
    return __uint_as_float(u);
}

// ---------------- group norm, channel-major (B,C,S), optional pos add ----------------
__global__ void gn_cmajor(const float* __restrict__ x, const float* __restrict__ g,
                          const float* __restrict__ be, const float* __restrict__ pos,
                          float* __restrict__ y) {
    __shared__ float sb[256];
    int tid = threadIdx.x;
    int b = blockIdx.x / NGR, gi = blockIdx.x % NGR;
    long base = (long)b * CCH * SS + (long)gi * CG * SS;
    float s1 = 0.f, s2 = 0.f;
    for (int i = tid; i < CG * SS; i += 256) { float v = x[base + i]; s1 += v; s2 += v * v; }
    s1 = blk_sum(s1, sb, tid);
    s2 = blk_sum(s2, sb, tid);
    float mu = s1 / (float)(CG * SS);
    float var = s2 / (float)(CG * SS) - mu * mu;
    float inv = rsqrtf(var + GEPS);
    for (int i = tid; i < CG * SS; i += 256) {
        int cl = i >> 10, s = i & 1023;
        int c = gi * CG + cl;
        float v = (x[base + i] - mu) * inv * g[c] + be[c];
        if (pos) v += pos[(long)c * SS + s];
        y[base + i] = v;
    }
}

// ---------------- group norm token-major + residual, out (B,C,S) ----------------
__global__ void gn_post_k(const float* __restrict__ xt, const float* __restrict__ g,
                          const float* __restrict__ be, const float* __restrict__ resid,
                          float* __restrict__ y) {
    __shared__ float sb[256];
    int tid = threadIdx.x;
    int b = blockIdx.x / NGR, gi = blockIdx.x % NGR;
    long tbase = (long)b * SS * CCH + gi * CG;
    float s1 = 0.f, s2 = 0.f;
    for (int i = tid; i < CG * SS; i += 256) {
        int s = i >> 4, cl = i & 15;
        float v = xt[tbase + (long)s * CCH + cl]; s1 += v; s2 += v * v;
    }
    s1 = blk_sum(s1, sb, tid);
    s2 = blk_sum(s2, sb, tid);
    float mu = s1 / (float)(CG * SS);
    float var = s2 / (float)(CG * SS) - mu * mu;
    float inv = rsqrtf(var + GEPS);
    for (int i = tid; i < CG * SS; i += 256) {
        int s = i >> 4, cl = i & 15;
        int c = gi * CG + cl;
        float v = (xt[tbase + (long)s * CCH + cl] - mu) * inv * g[c] + be[c];
        long oidx = (long)b * CCH * SS + (long)c * SS + s;
        y[oidx] = v + resid[oidx];
    }
}

// =====================================================================
// Tensor-core tf32 GEMM, register double-buffered.
// Block tile 128x64, BK=32, 256 threads (8 warps 4x2), warp tile 32x32.
// MODE 0 (NT): A[m*lda+k],  B[n*ldb+k]
// MODE 1 (TN): A[k*lda+m],  B[n*ldb+k]
// MODE 2 (NN): A[m*lda+k],  B[k*ldb+n]
// =====================================================================
template<int MODE>
__global__ __launch_bounds__(256) void gemm_tc(
        const float* __restrict__ A, long aOuter, long aInner,
        const float* __restrict__ Bm, long bOuter, long bInner,
        const float* __restrict__ bias,
        float* __restrict__ Y, long yOuter, long yInner,
        int innerCnt, int K, int lda, int ldb, int ldy,
        float scale, int act) {
    __shared__ float smem[6912];
    float* As = smem;
    float* Bs = smem + (MODE == 1 ? 32 * 136 : 128 * 36);

    int z = blockIdx.z;
    const float* Ab = A  + (long)(z / innerCnt) * aOuter + (long)(z % innerCnt) * aInner;
    const float* Bb = Bm + (long)(z / innerCnt) * bOuter + (long)(z % innerCnt) * bInner;
    float*       Yb = Y  + (long)(z / innerCnt) * yOuter + (long)(z % innerCnt) * yInner;
    int m0 = blockIdx.x * 128, n0 = blockIdx.y * 64;

    int tid = threadIdx.x;
    int w = tid >> 5, lane = tid & 31;
    int wm = w & 3, wn = w >> 2;
    int g = lane >> 2, tig = lane & 3;
    int rbase = wm * 32, cbase = wn * 32;

    float acc[2][4][4];
    #pragma unroll
    for (int i = 0; i < 2; i++)
        #pragma unroll
        for (int j = 0; j < 4; j++)
            #pragma unroll
            for (int l = 0; l < 4; l++) acc[i][j][l] = 0.f;

    float4 aR[4], bR[2];

    auto ldgA = [&](int k0) {
        if (MODE == 1) {
            int mm = (tid & 31) * 4, kb = tid >> 5;
            #pragma unroll
            for (int it = 0; it < 4; it++)
                aR[it] = *(const float4*)&Ab[(long)(k0 + kb + it * 8) * lda + m0 + mm];
        } else {
            int kk = (tid & 7) * 4, mb = tid >> 3;
            #pragma unroll
            for (int it = 0; it < 4; it++)
                aR[it] = *(const float4*)&Ab[(long)(m0 + mb + it * 32) * lda + k0 + kk];
        }
    };
    auto ldgB = [&](int k0) {
        if (MODE == 2) {
            int nn = (tid & 15) * 4, kb = tid >> 4;
            #pragma unroll
            for (int it = 0; it < 2; it++)
                bR[it] = *(const float4*)&Bb[(long)(k0 + kb + it * 16) * ldb + n0 + nn];
        } else {
            int kk = (tid & 7) * 4, nb = tid >> 3;
            #pragma unroll
            for (int it = 0; it < 2; it++)
                bR[it] = *(const float4*)&Bb[(long)(n0 + nb + it * 32) * ldb + k0 + kk];
        }
    };
    auto stsAB = [&]() {
        if (MODE == 1) {
            int mm = (tid & 31) * 4, kb = tid >> 5;
            #pragma unroll
            for (int it = 0; it < 4; it++) {
                float4 v = aR[it];
                v.x = f2tf(v.x); v.y = f2tf(v.y); v.z = f2tf(v.z); v.w = f2tf(v.w);
                *(float4*)&As[(kb + it * 8) * 136 + mm] = v;
            }
        } else {
            int kk = (tid & 7) * 4, mb = tid >> 3;
            #pragma unroll
            for (int it = 0; it < 4; it++) {
                float4 v = aR[it];
                v.x = f2tf(v.x); v.y = f2tf(v.y); v.z = f2tf(v.z); v.w = f2tf(v.w);
                *(float4*)&As[(mb + it * 32) * 36 + kk] = v;
            }
        }
        if (MODE == 2) {
            int nn = (tid & 15) * 4, kb = tid >> 4;
            #pragma unroll
            for (int it = 0; it < 2; it++) {
                float4 v = bR[it];
                v.x = f2tf(v.x); v.y = f2tf(v.y); v.z = f2tf(v.z); v.w = f2tf(v.w);
                *(float4*)&Bs[(kb + it * 16) * 68 + nn] = v;
            }
        } else {
            int kk = (tid & 7) * 4, nb = tid >> 3;
            #pragma unroll
            for (int it = 0; it < 2; it++) {
                float4 v = bR[it];
                v.x = f2tf(v.x); v.y = f2tf(v.y); v.z = f2tf(v.z); v.w = f2tf(v.w);
                *(float4*)&Bs[(nb + it * 32) * 36 + kk] = v;
            }
        }
    };

    ldgA(0); ldgB(0);
    for (int k0 = 0; k0 < K; k0 += 32) {
        stsAB();
        __syncthreads();
        if (k0 + 32 < K) { ldgA(k0 + 32); ldgB(k0 + 32); }

        #pragma unroll
        for (int ks = 0; ks < 4; ks++) {
            int kk = ks * 8 + tig, kk2 = kk + 4;
            uint32_t af[2][4], bf[4][2];
            #pragma unroll
            for (int mt = 0; mt < 2; mt++) {
                int r = rbase + mt * 16 + g;
                if (MODE == 1) {
                    af[mt][0] = __float_as_uint(As[kk  * 136 + r]);
                    af[mt][1] = __float_as_uint(As[kk  * 136 + r + 8]);
                    af[mt][2] = __float_as_uint(As[kk2 * 136 + r]);
                    af[mt][3] = __float_as_uint(As[kk2 * 136 + r + 8]);
                } else {
                    af[mt][0] = __float_as_uint(As[r       * 36 + kk]);
                    af[mt][1] = __float_as_uint(As[(r + 8) * 36 + kk]);
                    af[mt][2] = __float_as_uint(As[r       * 36 + kk2]);
                    af[mt][3] = __float_as_uint(As[(r + 8) * 36 + kk2]);
                }
            }
            #pragma unroll
            for (int nt = 0; nt < 4; nt++) {
                int cN = cbase + nt * 8 + g;
                if (MODE == 2) {
                    bf[nt][0] = __float_as_uint(Bs[kk  * 68 + cN]);
                    bf[nt][1] = __float_as_uint(Bs[kk2 * 68 + cN]);
                } else {
                    bf[nt][0] = __float_as_uint(Bs[cN * 36 + kk]);
                    bf[nt][1] = __float_as_uint(Bs[cN * 36 + kk2]);
                }
            }
            #pragma unroll
            for (int mt = 0; mt < 2; mt++)
                #pragma unroll
                for (int nt = 0; nt < 4; nt++) {
                    asm volatile(
                        "mma.sync.aligned.m16n8k8.row.col.f32.tf32.tf32.f32 "
                        "{%0,%1,%2,%3},{%4,%5,%6,%7},{%8,%9},{%0,%1,%2,%3};"
                        : "+f"(acc[mt][nt][0]), "+f"(acc[mt][nt][1]),
                          "+f"(acc[mt][nt][2]), "+f"(acc[mt][nt][3])
                        : "r"(af[mt][0]), "r"(af[mt][1]), "r"(af[mt][2]), "r"(af[mt][3]),
                          "r"(bf[nt][0]), "r"(bf[nt][1]));
                }
        }
        __syncthreads();
    }

    #pragma unroll
    for (int mt = 0; mt < 2; mt++) {
        #pragma unroll
        for (int nt = 0; nt < 4; nt++) {
            int r = m0 + rbase + mt * 16 + g;
            int cN = n0 + cbase + nt * 8 + 2 * tig;
            float b0 = bias ? bias[cN] : 0.f;
            float b1 = bias ? bias[cN + 1] : 0.f;
            float v0 = acc[mt][nt][0] * scale + b0;
            float v1 = acc[mt][nt][1] * scale + b1;
            float v2 = acc[mt][nt][2] * scale + b0;
            float v3 = acc[mt][nt][3] * scale + b1;
            if (act == 1) { v0 = silu_f(v0); v1 = silu_f(v1); v2 = silu_f(v2); v3 = silu_f(v3); }
            *(float2*)&Yb[(long)r * ldy + cN]       = make_float2(v0, v1);
            *(float2*)&Yb[(long)(r + 8) * ldy + cN] = make_float2(v2, v3);
        }
    }
}

// =====================================================================
// Flash attention, std MHA: HD=64, S=1024. q-tile 128, key-chunk 64.
// 256 threads = 8 warps (4m x 2n). Online softmax, P staged via smem
// (overlaying the K tile). Output written to comb (ld = 1024).
// =====================================================================
#define FLASH_SMEM_FLOATS (8704 + 8704 + 4352 + 256 + 256)
__global__ __launch_bounds__(256) void flash_std(
        const float* __restrict__ Q, const float* __restrict__ K,
        const float* __restrict__ V, float* __restrict__ O) {
    extern __shared__ float sm[];
    float* Qs  = sm;                 // [128][68] m-major, pre-scaled, tf32
    float* KPs = sm + 8704;          // Ks [64][68] n-major, then Ps [128][68]
    float* Vs  = sm + 2 * 8704;      // [64][68] k-major (key, hd)
    float* redm = sm + 2 * 8704 + 4352;  // [2][128]
    float* redl = redm + 256;            // [2][128]

    int bh = blockIdx.z;
    int b = bh >> 3, h = bh & 7;
    const float* Qb = Q + (long)b * SS * CCH + h * 64;
    const float* Kb = K + (long)b * SS * CCH + h * 64;
    const float* Vb = V + (long)b * SS * CCH + h * 64;
    float* Ob = O + (long)b * SS * (2 * CCH) + h * 64;
    int q0 = blockIdx.x * 128;

    int tid = threadIdx.x;
    int w = tid >> 5, lane = tid & 31;
    int wm = w & 3, wn = w >> 2;
    int g = lane >> 2, tig = lane & 3;
    int rbase = wm * 32, cbase = wn * 32;

    // stage Q (scaled by 1/sqrt(64)=0.125)
    #pragma unroll
    for (int f = 0; f < 8; f++) {
        int idx = tid + f * 256;
        int r = idx >> 4, kq = (idx & 15) * 4;
        float4 v4 = *(const float4*)&Qb[(long)(q0 + r) * CCH + kq];
        v4.x = f2tf(v4.x * 0.125f); v4.y = f2tf(v4.y * 0.125f);
        v4.z = f2tf(v4.z * 0.125f); v4.w = f2tf(v4.w * 0.125f);
        *(float4*)&Qs[r * 68 + kq] = v4;
    }

    float accO[2][4][4];
    #pragma unroll
    for (int i = 0; i < 2; i++)
        #pragma unroll
        for (int j = 0; j < 4; j++)
            #pragma unroll
            for (int l = 0; l < 4; l++) accO[i][j][l] = 0.f;
    float mst[4] = { -1e30f, -1e30f, -1e30f, -1e30f };
    float lst[4] = { 0.f, 0.f, 0.f, 0.f };

    for (int j = 0; j < 16; j++) {
        __syncthreads();   // prev PV done (and Qs staged on first iter)
        // stage K, V chunk (64 keys x 64)
        #pragma unroll
        for (int f = 0; f < 4; f++) {
            int idx = tid + f * 256;
            int key = idx >> 4, kq = (idx & 15) * 4;
            long goff = (long)(j * 64 + key) * CCH + kq;
            float4 kv = *(const float4*)&Kb[goff];
            kv.x = f2tf(kv.x); kv.y = f2tf(kv.y); kv.z = f2tf(kv.z); kv.w = f2tf(kv.w);
            *(float4*)&KPs[key * 68 + kq] = kv;
            float4 vv = *(const float4*)&Vb[goff];
            vv.x = f2tf(vv.x); vv.y = f2tf(vv.y); vv.z = f2tf(vv.z); vv.w = f2tf(vv.w);
            *(float4*)&Vs[key * 68 + kq] = vv;
        }
        __syncthreads();

        // S = Q K^T  (128x64 tile, K-dim 64)
        float acc[2][4][4];
        #pragma unroll
        for (int i = 0; i < 2; i++)
            #pragma unroll
            for (int jj = 0; jj < 4; jj++)
                #pragma unroll
                for (int l = 0; l < 4; l++) acc[i][jj][l] = 0.f;
        #pragma unroll
        for (int ks = 0; ks < 8; ks++) {
            int kk = ks * 8 + tig, kk2 = kk + 4;
            uint32_t af[2][4], bf[4][2];
            #pragma unroll
            for (int mt = 0; mt < 2; mt++) {
                int r = rbase + mt * 16 + g;
                af[mt][0] = __float_as_uint(Qs[r       * 68 + kk]);
                af[mt][1] = __float_as_uint(Qs[(r + 8) * 68 + kk]);
                af[mt][2] = __float_as_uint(Qs[r       * 68 + kk2]);
                af[mt][3] = __float_as_uint(Qs[(r + 8) * 68 + kk2]);
            }
            #pragma unroll
            for (int nt = 0; nt < 4; nt++) {
                int cN = cbase + nt * 8 + g;
                bf[nt][0] = __float_as_uint(KPs[cN * 68 + kk]);
                bf[nt][1] = __float_as_uint(KPs[cN * 68 + kk2]);
            }
            #pragma unroll
            for (int mt = 0; mt < 2; mt++)
                #pragma unroll
                for (int nt = 0; nt < 4; nt++) {
                    asm volatile(
                        "mma.sync.aligned.m16n8k8.row.col.f32.tf32.tf32.f32 "
                        "{%0,%1,%2,%3},{%4,%5,%6,%7},{%8,%9},{%0,%1,%2,%3};"
                        : "+f"(acc[mt][nt][0]), "+f"(acc[mt][nt][1]),
                          "+f"(acc[mt][nt][2]), "+f"(acc[mt][nt][3])
                        : "r"(af[mt][0]), "r"(af[mt][1]), "r"(af[mt][2]), "r"(af[mt][3]),
                          "r"(bf[nt][0]), "r"(bf[nt][1]));
                }
        }

        // row max (this warp's 32-col half)
        float wmax[4];
        #pragma unroll
        for (int mt = 0; mt < 2; mt++)
            #pragma unroll
            for (int hh = 0; hh < 2; hh++) {
                float mx = -1e30f;
                #pragma unroll
                for (int nt = 0; nt < 4; nt++) {
                    mx = fmaxf(mx, acc[mt][nt][hh * 2]);
                    mx = fmaxf(mx, acc[mt][nt][hh * 2 + 1]);
                }
                mx = fmaxf(mx, __shfl_xor_sync(0xffffffffu, mx, 1));
                mx = fmaxf(mx, __shfl_xor_sync(0xffffffffu, mx, 2));
                wmax[mt * 2 + hh] = mx;
                if (tig == 0) redm[wn * 128 + rbase + mt * 16 + hh * 8 + g] = mx;
            }
        __syncthreads();

        // exp, write P (overlays Ks), local sums, rescale O
        #pragma unroll
        for (int mt = 0; mt < 2; mt++)
            #pragma unroll
            for (int hh = 0; hh < 2; hh++) {
                int i = mt * 2 + hh;
                int rloc = rbase + mt * 16 + hh * 8 + g;
                float mch = fmaxf(redm[rloc], redm[128 + rloc]);
                float mnew = fmaxf(mst[i], mch);
                float corr = __expf(mst[i] - mnew);
                mst[i] = mnew;
                float s = 0.f;
                #pragma unroll
                for (int nt = 0; nt < 4; nt++) {
                    float p0 = __expf(acc[mt][nt][hh * 2]     - mnew);
                    float p1 = __expf(acc[mt][nt][hh * 2 + 1] - mnew);
                    s += p0 + p1;
                    int col = cbase + nt * 8 + 2 * tig;
                    *(float2*)&KPs[rloc * 68 + col] = make_float2(f2tf(p0), f2tf(p1));
                    accO[mt][nt][hh * 2]     *= corr;
                    accO[mt][nt][hh * 2 + 1] *= corr;
                }
                s += __shfl_xor_sync(0xffffffffu, s, 1);
                s += __shfl_xor_sync(0xffffffffu, s, 2);
                if (tig == 0) redl[wn * 128 + rloc] = s;
                lst[i] *= corr;
            }
        __syncthreads();
        #pragma unroll
        for (int mt = 0; mt < 2; mt++)
            #pragma unroll
            for (int hh = 0; hh < 2; hh++) {
                int rloc = rbase + mt * 16 + hh * 8 + g;
                lst[mt * 2 + hh] += redl[rloc] + redl[128 + rloc];
            }

        // O += P V   (A = Ps m-major over keys, B = Vs k-major)
        #pragma unroll
        for (int ks = 0; ks < 8; ks++) {
            int kk = ks * 8 + tig, kk2 = kk + 4;
            uint32_t af[2][4], bf[4][2];
            #pragma unroll
            for (int mt = 0; mt < 2; mt++) {
                int r = rbase + mt * 16 + g;
                af[mt][0] = __float_as_uint(KPs[r       * 68 + kk]);
                af[mt][1] = __float_as_uint(KPs[(r + 8) * 68 + kk]);
                af[mt][2] = __float_as_uint(KPs[r       * 68 + kk2]);
                af[mt][3] = __float_as_uint(KPs[(r + 8) * 68 + kk2]);
            }
            #pragma unroll
            for (int nt = 0; nt < 4; nt++) {
                int cN = cbase + nt * 8 + g;
                bf[nt][0] = __float_as_uint(Vs[kk  * 68 + cN]);
                bf[nt][1] = __float_as_uint(Vs[kk2 * 68 + cN]);
            }
            #pragma unroll
            for (int mt = 0; mt < 2; mt++)
                #pragma unroll
                for (int nt = 0; nt < 4; nt++) {
                    asm volatile(
                        "mma.sync.aligned.m16n8k8.row.col.f32.tf32.tf32.f32 "
                        "{%0,%1,%2,%3},{%4,%5,%6,%7},{%8,%9},{%0,%1,%2,%3};"
                        : "+f"(accO[mt][nt][0]), "+f"(accO[mt][nt][1]),
                          "+f"(accO[mt][nt][2]), "+f"(accO[mt][nt][3])
                        : "r"(af[mt][0]), "r"(af[mt][1]), "r"(af[mt][2]), "r"(af[mt][3]),
                          "r"(bf[nt][0]), "r"(bf[nt][1]));
                }
        }
    }

    // epilogue: O /= l
    #pragma unroll
    for (int mt = 0; mt < 2; mt++) {
        float inv0 = 1.0f / lst[mt * 2];
        float inv1 = 1.0f / lst[mt * 2 + 1];
        #pragma unroll
        for (int nt = 0; nt < 4; nt++) {
            int r = q0 + rbase + mt * 16 + g;
            int c = cbase + nt * 8 + 2 * tig;
            *(float2*)&Ob[(long)r * 1024 + c] =
                make_float2(accO[mt][nt][0] * inv0, accO[mt][nt][1] * inv0);
            *(float2*)&Ob[(long)(r + 8) * 1024 + c] =
                make_float2(accO[mt][nt][2] * inv1, accO[mt][nt][3] * inv1);
        }
    }
}

// ---------------- softmax over rows of length 1024 ----------------
__global__ void softmax1024(float* __restrict__ p) {
    __shared__ float sb[256];
    long r = blockIdx.x;
    float* row = p + r * 1024;
    int tid = threadIdx.x;
    float4 v = *(float4*)&row[tid * 4];
    float m = fmaxf(fmaxf(v.x, v.y), fmaxf(v.z, v.w));
    m = blk_max(m, sb, tid);
    v.x = __expf(v.x - m); v.y = __expf(v.y - m);
    v.z = __expf(v.z - m); v.w = __expf(v.w - m);
    float s = v.x + v.y + v.z + v.w;
    s = blk_sum(s, sb, tid);
    float inv = 1.0f / s;
    v.x *= inv; v.y *= inv; v.z *= inv; v.w *= inv;
    *(float4*)&row[tid * 4] = v;
}

// ---------------- conv 1x1 (512 -> 64) + SiLU ----------------
__global__ void conv1_silu(const float* __restrict__ x, const float* __restrict__ w,
                           const float* __restrict__ bias, float* __restrict__ y) {
    __shared__ float ws[8 * 512];
    int tid = threadIdx.x;
    int o0 = blockIdx.y * 8, b = blockIdx.z;
    for (int i = tid; i < 8 * 512; i += 256) ws[i] = w[(long)o0 * 512 + i];
    __syncthreads();
    int s = blockIdx.x * 256 + tid;
    float acc[8];
    #pragma unroll
    for (int oo = 0; oo < 8; oo++) acc[oo] = bias[o0 + oo];
    const float* xb = x + (long)b * CCH * SS + s;
    for (int c = 0; c < 512; c++) {
        float xv = xb[(long)c * SS];
        #pragma unroll
        for (int oo = 0; oo < 8; oo++) acc[oo] += xv * ws[oo * 512 + c];
    }
    #pragma unroll
    for (int oo = 0; oo < 8; oo++)
        y[(long)b * C8 * SS + (long)(o0 + oo) * SS + s] = silu_f(acc[oo]);
}

// ---------------- conv 3x3 (64 -> 64, SAME) + SiLU ----------------
__global__ void conv2_silu(const float* __restrict__ x, const float* __restrict__ w,
                           const float* __restrict__ bias, float* __restrict__ y) {
    __shared__ float ws[8 * 576];
    int tid = threadIdx.x;
    int o0 = blockIdx.y * 8, b = blockIdx.z;
    for (int i = tid; i < 8 * 576; i += 256) ws[i] = w[(long)o0 * 576 + i];
    __syncthreads();
    int s = blockIdx.x * 256 + tid;
    int yy = s >> 5, xx = s & 31;
    float acc[8];
    #pragma unroll
    for (int oo = 0; oo < 8; oo++) acc[oo] = bias[o0 + oo];
    const float* xb = x + (long)b * C8 * SS;
    for (int ci = 0; ci < 64; ci++) {
        #pragma unroll
        for (int ky = 0; ky < 3; ky++) {
            int py = yy + ky - 1;
            if (py < 0 || py >= 32) continue;
            #pragma unroll
            for (int kx = 0; kx < 3; kx++) {
                int px = xx + kx - 1;
                if (px < 0 || px >= 32) continue;
                float av = xb[(long)ci * SS + py * 32 + px];
                #pragma unroll
                for (int oo = 0; oo < 8; oo++)
                    acc[oo] += av * ws[oo * 576 + ci * 9 + ky * 3 + kx];
            }
        }
    }
    #pragma unroll
    for (int oo = 0; oo < 8; oo++)
        y[(long)b * C8 * SS + (long)(o0 + oo) * SS + s] = silu_f(acc[oo]);
}

// ---------------- conv 1x1 (64 -> 1) + sigmoid ----------------
__global__ void conv3_sig(const float* __restrict__ x, const float* __restrict__ w,
                          const float* __restrict__ bias, float* __restrict__ y) {
    int idx = blockIdx.x * 256 + threadIdx.x;
    int b = idx >> 10, s = idx & 1023;
    float acc = bias[0];
    const float* xb = x + (long)b * C8 * SS + s;
    #pragma unroll 8
    for (int i = 0; i < 64; i++) acc += xb[(long)i * SS] * w[i];
    y[idx] = 1.0f / (1.0f + expf(-acc));
}

// ---------------- spatial_enhanced = hs * sw ----------------
__global__ void senh_mul(const float* __restrict__ hs, const float* __restrict__ sw,
                         float* __restrict__ y) {
    long idx = (long)blockIdx.x * 256 + threadIdx.x;
    int b = (int)(idx >> 19);
    int s = (int)(idx & 1023);
    y[idx] = hs[idx] * sw[b * 1024 + s];
}

// ---------------- launch ----------------
static float* sym(const void* s) { void* p = nullptr; cudaGetSymbolAddress(&p, s); return (float*)p; }

extern "C" void kernel_launch(void* const* d_in, const int* in_sizes, int n_in,
                              void* d_out, int out_size) {
    (void)in_sizes; (void)n_in; (void)out_size;
    const float* x      = (const float*)d_in[0];
    const float* pre_g  = (const float*)d_in[1];
    const float* pre_b  = (const float*)d_in[2];
    const float* norm_g = (const float*)d_in[3];
    const float* norm_b = (const float*)d_in[4];
    const float* post_g = (const float*)d_in[5];
    const float* post_b = (const float*)d_in[6];
    const float* pos    = (const float*)d_in[7];
    const float* sa_w1  = (const float*)d_in[8];
    const float* sa_b1  = (const float*)d_in[9];
    const float* sa_w2  = (const float*)d_in[10];
    const float* sa_b2  = (const float*)d_in[11];
    const float* sa_w3  = (const float*)d_in[12];
    const float* sa_b3  = (const float*)d_in[13];
    const float* wq     = (const float*)d_in[14];
    const float* wk     = (const float*)d_in[15];
    const float* wv     = (const float*)d_in[16];
    const float* wqm[2] = { (const float*)d_in[17], (const float*)d_in[20] };
    const float* wkm[2] = { (const float*)d_in[18], (const float*)d_in[21] };
    const float* wvm[2] = { (const float*)d_in[19], (const float*)d_in[22] };
    const float* ff_w1  = (const float*)d_in[23];
    const float* ff_b1  = (const float*)d_in[24];
    const float* ff_w2  = (const float*)d_in[25];
    const float* ff_b2  = (const float*)d_in[26];
    const float* out_w  = (const float*)d_in[27];
    const float* out_b  = (const float*)d_in[28];
    float* out = (float*)d_out;

    float *hs = sym(d_hs), *shn = sym(d_shn), *senh = sym(d_senh);
    float *a1 = sym(d_a1), *a2 = sym(d_a2), *sw = sym(d_swt);
    float *q = sym(d_q), *k = sym(d_k), *v = sym(d_v);
    float *qm = sym(d_qm), *km = sym(d_km), *vm = sym(d_vm);
    float *comb = sym(d_comb), *f1 = sym(d_f1), *fus = sym(d_fus), *fin = sym(d_fin);
    float *scm = sym(d_scm);

    const int flashSmem = FLASH_SMEM_FLOATS * 4;
    cudaFuncSetAttribute(flash_std, cudaFuncAttributeMaxDynamicSharedMemorySize, flashSmem);

    gn_cmajor<<<BATCH * NGR, 256>>>(x, pre_g, pre_b, pos, hs);
    conv1_silu<<<dim3(4, 8, BATCH), 256>>>(hs, sa_w1, sa_b1, a1);
    conv2_silu<<<dim3(4, 8, BATCH), 256>>>(a1, sa_w2, sa_b2, a2);
    conv3_sig<<<BATCH * SS / 256, 256>>>(a2, sa_w3, sa_b3, sw);
    senh_mul<<<BATCH * CCH * SS / 256, 256>>>(hs, sw, senh);
    gn_cmajor<<<BATCH * NGR, 256>>>(hs, norm_g, norm_b, nullptr, shn);

    // QKV projections (TN)
    gemm_tc<1><<<dim3(8, 8, BATCH), 256>>>(shn, (long)CCH * SS, 0, wq, 0, 0, nullptr,
                                           q, (long)SS * CCH, 0, 1, 512, SS, 512, 512, 1.f, 0);
    gemm_tc<1><<<dim3(8, 8, BATCH), 256>>>(shn, (long)CCH * SS, 0, wk, 0, 0, nullptr,
                                           k, (long)SS * CCH, 0, 1, 512, SS, 512, 512, 1.f, 0);
    gemm_tc<1><<<dim3(8, 8, BATCH), 256>>>(shn, (long)CCH * SS, 0, wv, 0, 0, nullptr,
                                           v, (long)SS * CCH, 0, 1, 512, SS, 512, 512, 1.f, 0);
    // multi-scale projections
    for (int br = 0; br < 2; br++) {
        long off = (long)br * BATCH * SS * C2;
        gemm_tc<1><<<dim3(8, 4, BATCH), 256>>>(senh, (long)CCH * SS, 0, wqm[br], 0, 0, nullptr,
                                               qm + off, (long)SS * C2, 0, 1, 512, SS, 512, 256, 1.f, 0);
        gemm_tc<1><<<dim3(8, 4, BATCH), 256>>>(shn, (long)CCH * SS, 0, wkm[br], 0, 0, nullptr,
                                               km + off, (long)SS * C2, 0, 1, 512, SS, 512, 256, 1.f, 0);
        gemm_tc<1><<<dim3(8, 4, BATCH), 256>>>(shn, (long)CCH * SS, 0, wvm[br], 0, 0, nullptr,
                                               vm + off, (long)SS * C2, 0, 1, 512, SS, 512, 256, 1.f, 0);
    }

    // std MHA: fused flash attention -> comb[:, :, 0:512]
    flash_std<<<dim3(8, 1, BATCH * NHD), 256, flashSmem>>>(q, k, v, comb);

    // multi scores (NT, 16 batch-branches)
    gemm_tc<0><<<dim3(8, 16, 16), 256>>>(qm, (long)SS * C2, 0, km, (long)SS * C2, 0, nullptr,
                                         scm, (long)SS * SS, 0, 1,
                                         C2, C2, C2, SS, 0.0625f, 0);
    softmax1024<<<16 * SS, 256>>>(scm);
    // multi P @ V (NN)
    gemm_tc<2><<<dim3(8, 4, 16), 256>>>(scm, 8LL * SS * SS, (long)SS * SS,
                                        vm, 8LL * SS * C2, (long)SS * C2, nullptr,
                                        comb + CCH, (long)C2, (long)SS * 2 * CCH, 8,
                                        SS, SS, C2, 2 * CCH, 1.f, 0);
    // ff1 (silu)
    gemm_tc<0><<<dim3(8, 8, BATCH), 256>>>(comb, (long)SS * 2 * CCH, 0, ff_w1, 0, 0, ff_b1,
                                           f1, (long)SS * CCH, 0, 1,
                                           2 * CCH, 2 * CCH, 2 * CCH, CCH, 1.f, 1);
    // ff2
    gemm_tc<0><<<dim3(8, 8, BATCH), 256>>>(f1, (long)SS * CCH, 0, ff_w2, 0, 0, ff_b2,
                                           fus, (long)SS * CCH, 0, 1,
                                           CCH, CCH, CCH, CCH, 1.f, 0);
    // out proj
    gemm_tc<0><<<dim3(8, 8, BATCH), 256>>>(fus, (long)SS * CCH, 0, out_w, 0, 0, out_b,
                                           fin, (long)SS * CCH, 0, 1,
                                           CCH, CCH, CCH, CCH, 1.f, 0);
    gn_post_k<<<BATCH * NGR, 256>>>(fin, post_g, post_b, x, out);
}